// round 2
// baseline (speedup 1.0000x reference)
#include <cuda_runtime.h>
#include <math.h>

#define NN 40000
#define EE 640000
#define D  128
#define DOUT 40
#define GR 64                 // gemm rows per block
#define HBITS 21
#define HSIZE (1 << HBITS)
#define HMASK (HSIZE - 1)

// ---------------- scratch (static device globals; no allocation) ------------
__device__ int   g_degE[NN];
__device__ float g_dis[NN];
__device__ int   g_rowptr[NN + 1];
__device__ int   g_cursor[NN];
__device__ int   g_csrc[EE];
__device__ float g_cnorm[EE];
__device__ float g_h [NN * D];
__device__ float g_y [NN * D];
__device__ float g_h3[NN * DOUT];
__device__ int   g_hk[HSIZE];
__device__ int   g_hc[HSIZE];
__device__ unsigned int g_reg;

// ---------------- init: reset per-call state --------------------------------
__global__ void k_init() {
    int i = blockIdx.x * blockDim.x + threadIdx.x;
    int stride = gridDim.x * blockDim.x;
    for (int j = i; j < HSIZE; j += stride) { g_hk[j] = -1; g_hc[j] = 0; }
    for (int j = i; j < NN; j += stride) g_degE[j] = 0;
    if (i == 0) g_reg = 0u;
}

__device__ __forceinline__ unsigned int hmix(unsigned int k) {
    k *= 2654435761u;
    k ^= k >> 15;
    return k;
}

// ---------------- edge pass 1: degree histogram + hash insert ---------------
__global__ void k_edge1(const int* __restrict__ src, const int* __restrict__ dst,
                        int E, int n) {
    int e = blockIdx.x * blockDim.x + threadIdx.x;
    if (e >= E) return;
    int s = src[e], d = dst[e];
    atomicAdd(&g_degE[d], 1);
    unsigned int key = (unsigned int)s * (unsigned int)n + (unsigned int)d;
    unsigned int slot = hmix(key) & HMASK;
    while (true) {
        int old = atomicCAS(&g_hk[slot], -1, (int)key);
        if (old == -1 || old == (int)key) { atomicAdd(&g_hc[slot], 1); break; }
        slot = (slot + 1) & HMASK;
    }
}

// ---------------- 1-block exclusive scan + dis + cursor ---------------------
__global__ void k_scan(int n, int E) {
    __shared__ int sm[1024];
    int t = threadIdx.x;
    int chunk = (n + 1023) / 1024;
    int lo = t * chunk;
    int hi = lo + chunk; if (hi > n) hi = n;
    int s = 0;
    for (int i = lo; i < hi; i++) s += g_degE[i];
    sm[t] = s;
    __syncthreads();
    for (int off = 1; off < 1024; off <<= 1) {
        int v = (t >= off) ? sm[t - off] : 0;
        __syncthreads();
        sm[t] += v;
        __syncthreads();
    }
    int base = sm[t] - s;  // exclusive prefix
    for (int i = lo; i < hi; i++) {
        int d = g_degE[i];
        g_rowptr[i] = base;
        g_cursor[i] = base;
        g_dis[i] = rsqrtf((float)(d + 1));  // +1 self loop
        base += d;
    }
    if (t == 1023) g_rowptr[n] = E;
}

// ---------------- edge pass 2: CSR scatter + reverse-key lookup -------------
__global__ void k_edge2(const int* __restrict__ src, const int* __restrict__ dst,
                        int E, int n) {
    int e = blockIdx.x * blockDim.x + threadIdx.x;
    if (e >= E) return;
    int s = src[e], d = dst[e];
    int pos = atomicAdd(&g_cursor[d], 1);
    g_csrc[pos]  = s;
    g_cnorm[pos] = g_dis[s] * g_dis[d];

    unsigned int rkey = (unsigned int)d * (unsigned int)n + (unsigned int)s;
    unsigned int slot = hmix(rkey) & HMASK;
    int c = 0;
    while (true) {
        int k = g_hk[slot];
        if (k == -1) break;
        if (k == (int)rkey) { c = g_hc[slot]; break; }
        slot = (slot + 1) & HMASK;
    }
    if (c) atomicAdd(&g_reg, (unsigned int)c);   // rare (~hundreds total)
}

// ---------------- SGEMM: [M,128] @ [128,128], no shuffles --------------------
// W (64KB) + 64-row X tile (32KB) in SMEM; thread = 8 rows x 4 cols.
__global__ __launch_bounds__(256) void k_gemm128(const float* __restrict__ X,
                                                 const float* __restrict__ W,
                                                 float* __restrict__ H, int M) {
    extern __shared__ float smf[];
    float* Ws = smf;            // D*D
    float* Xs = smf + D * D;    // GR*D
    for (int i = threadIdx.x; i < D * D; i += 256) Ws[i] = W[i];

    const int tx = threadIdx.x & 31;   // col group (4 cols)
    const int ty = threadIdx.x >> 5;   // row group (8 rows)

    for (int t0 = blockIdx.x * GR; t0 < M; t0 += gridDim.x * GR) {
        __syncthreads();
        const float4* Xg = (const float4*)(X + (size_t)t0 * D);
        float4* Xs4 = (float4*)Xs;
        for (int i = threadIdx.x; i < GR * (D / 4); i += 256) Xs4[i] = Xg[i];
        __syncthreads();

        float4 acc[8];
#pragma unroll
        for (int r = 0; r < 8; r++) acc[r] = make_float4(0.f, 0.f, 0.f, 0.f);

        const float* xrow = Xs + ty * 8 * D;
#pragma unroll 4
        for (int k = 0; k < D; k++) {
            float4 wv = *(const float4*)&Ws[k * D + tx * 4];
#pragma unroll
            for (int r = 0; r < 8; r++) {
                float xv = xrow[r * D + k];
                acc[r].x += xv * wv.x;
                acc[r].y += xv * wv.y;
                acc[r].z += xv * wv.z;
                acc[r].w += xv * wv.w;
            }
        }
        float4* Hg = (float4*)(H + (size_t)t0 * D);
#pragma unroll
        for (int r = 0; r < 8; r++)
            Hg[(ty * 8 + r) * (D / 4) + tx] = acc[r];
    }
}

// ---------------- SGEMM: [M,128] @ [128,40] (shuffle variant — A/B probe) ---
__global__ void k_gemm40(const float* __restrict__ X, const float* __restrict__ W,
                         float* __restrict__ H3, int M) {
    __shared__ float Ws[D * DOUT + 32];
    for (int i = threadIdx.x; i < D * DOUT + 32; i += blockDim.x)
        Ws[i] = (i < D * DOUT) ? W[i] : 0.f;
    __syncthreads();

    const int lane = threadIdx.x & 31;
    const int wid  = threadIdx.x >> 5;
    const int gw   = blockIdx.x * (blockDim.x >> 5) + wid;
    const int nw   = (blockDim.x >> 5) * gridDim.x;

    for (int r0 = gw * 4; r0 < M; r0 += nw * 4) {
        float xr[4][4];
#pragma unroll
        for (int r = 0; r < 4; r++) {
            const float* xp = X + (r0 + r) * D;
#pragma unroll
            for (int j = 0; j < 4; j++) xr[r][j] = xp[lane + 32 * j];
        }
        float a0[4] = {0.f, 0.f, 0.f, 0.f};
        float a1[4] = {0.f, 0.f, 0.f, 0.f};
#pragma unroll
        for (int j = 0; j < 4; j++) {
#pragma unroll 8
            for (int l = 0; l < 32; l++) {
                int k = j * 32 + l;
                float w0 = Ws[k * DOUT + lane];
                float w1 = Ws[k * DOUT + 32 + lane];
#pragma unroll
                for (int r = 0; r < 4; r++) {
                    float xk = __shfl_sync(0xffffffffu, xr[r][j], l);
                    a0[r] += xk * w0;
                    a1[r] += xk * w1;
                }
            }
        }
#pragma unroll
        for (int r = 0; r < 4; r++) {
            H3[(r0 + r) * DOUT + lane] = a0[r];
            if (lane < 8) H3[(r0 + r) * DOUT + 32 + lane] = a1[r];
        }
    }
}

// ---------------- aggregation (128-d) + bias + ReLU, warp per node ----------
__global__ __launch_bounds__(256) void k_agg128(const float* __restrict__ Hh,
                                                const float* __restrict__ b,
                                                float* __restrict__ Y, int n) {
    const int lane = threadIdx.x & 31;
    const int i = blockIdx.x * (blockDim.x >> 5) + (threadIdx.x >> 5);
    if (i >= n) return;

    const float4* __restrict__ H4 = (const float4*)Hh;
    float dsc = g_dis[i];
    float d2 = dsc * dsc;
    float4 acc = H4[(size_t)i * 32 + lane];
    acc.x *= d2; acc.y *= d2; acc.z *= d2; acc.w *= d2;

    int p  = g_rowptr[i];
    const int pe = g_rowptr[i + 1];

    for (; p + 4 <= pe; p += 4) {
        int   s0 = g_csrc[p],     s1 = g_csrc[p + 1];
        int   s2 = g_csrc[p + 2], s3 = g_csrc[p + 3];
        float w0 = g_cnorm[p],     w1 = g_cnorm[p + 1];
        float w2 = g_cnorm[p + 2], w3 = g_cnorm[p + 3];
        float4 v0 = H4[(size_t)s0 * 32 + lane];
        float4 v1 = H4[(size_t)s1 * 32 + lane];
        float4 v2 = H4[(size_t)s2 * 32 + lane];
        float4 v3 = H4[(size_t)s3 * 32 + lane];
        acc.x += w0 * v0.x + w1 * v1.x + w2 * v2.x + w3 * v3.x;
        acc.y += w0 * v0.y + w1 * v1.y + w2 * v2.y + w3 * v3.y;
        acc.z += w0 * v0.z + w1 * v1.z + w2 * v2.z + w3 * v3.z;
        acc.w += w0 * v0.w + w1 * v1.w + w2 * v2.w + w3 * v3.w;
    }
    for (; p < pe; p++) {
        int s = g_csrc[p];
        float w = g_cnorm[p];
        float4 v = H4[(size_t)s * 32 + lane];
        acc.x += w * v.x; acc.y += w * v.y; acc.z += w * v.z; acc.w += w * v.w;
    }

    float4 bb = *(const float4*)&b[lane * 4];
    acc.x = fmaxf(acc.x + bb.x, 0.f);
    acc.y = fmaxf(acc.y + bb.y, 0.f);
    acc.z = fmaxf(acc.z + bb.z, 0.f);
    acc.w = fmaxf(acc.w + bb.w, 0.f);
    ((float4*)Y)[(size_t)i * 32 + lane] = acc;
}

// ---------------- aggregation (40-d) + bias + log_softmax + reg write -------
__global__ __launch_bounds__(256) void k_agg40(const float* __restrict__ H3,
                                               const float* __restrict__ b,
                                               float* __restrict__ out, int n,
                                               int reg_idx) {
    if (blockIdx.x == 0 && threadIdx.x == 0) out[reg_idx] = (float)g_reg;

    const int lane = threadIdx.x & 31;
    const int i = blockIdx.x * (blockDim.x >> 5) + (threadIdx.x >> 5);
    if (i >= n) return;

    float dsc = g_dis[i];
    float d2 = dsc * dsc;
    float a0 = d2 * H3[(size_t)i * DOUT + lane];
    float a1 = (lane < 8) ? d2 * H3[(size_t)i * DOUT + 32 + lane] : 0.f;

    int p  = g_rowptr[i];
    const int pe = g_rowptr[i + 1];
    for (; p + 2 <= pe; p += 2) {
        int   s0 = g_csrc[p],  s1 = g_csrc[p + 1];
        float w0 = g_cnorm[p], w1 = g_cnorm[p + 1];
        a0 += w0 * H3[(size_t)s0 * DOUT + lane] + w1 * H3[(size_t)s1 * DOUT + lane];
        if (lane < 8)
            a1 += w0 * H3[(size_t)s0 * DOUT + 32 + lane] + w1 * H3[(size_t)s1 * DOUT + 32 + lane];
    }
    if (p < pe) {
        int s = g_csrc[p];
        float w = g_cnorm[p];
        a0 += w * H3[(size_t)s * DOUT + lane];
        if (lane < 8) a1 += w * H3[(size_t)s * DOUT + 32 + lane];
    }

    float v0 = a0 + b[lane];
    float v1 = (lane < 8) ? (a1 + b[32 + lane]) : -INFINITY;

    float m = fmaxf(v0, v1);
#pragma unroll
    for (int o = 16; o; o >>= 1) m = fmaxf(m, __shfl_xor_sync(0xffffffffu, m, o));
    float se = expf(v0 - m) + ((lane < 8) ? expf(v1 - m) : 0.f);
#pragma unroll
    for (int o = 16; o; o >>= 1) se += __shfl_xor_sync(0xffffffffu, se, o);
    float ls = m + logf(se);

    out[(size_t)i * DOUT + lane] = v0 - ls;
    if (lane < 8) out[(size_t)i * DOUT + 32 + lane] = v1 - ls;
}

// ---------------- launch ------------------------------------------------------
extern "C" void kernel_launch(void* const* d_in, const int* in_sizes, int n_in,
                              void* d_out, int out_size) {
    const float* x  = (const float*)d_in[0];
    const int*   ei = (const int*)d_in[1];
    const float* W1 = (const float*)d_in[2];
    const float* b1 = (const float*)d_in[3];
    const float* W2 = (const float*)d_in[4];
    const float* b2 = (const float*)d_in[5];
    const float* W3 = (const float*)d_in[6];
    const float* b3 = (const float*)d_in[7];
    float* out = (float*)d_out;

    const int n = in_sizes[0] / D;      // 40000
    const int E = in_sizes[1] / 2;      // 640000
    const int* src = ei;
    const int* dst = ei + E;

    const int GEMM_SMEM = (D * D + GR * D) * sizeof(float);  // 96 KB
    cudaFuncSetAttribute(k_gemm128, cudaFuncAttributeMaxDynamicSharedMemorySize, GEMM_SMEM);

    const int TB = 256;
    const int eblocks = (E + TB - 1) / TB;
    const int wblocks = (n + (TB / 32) - 1) / (TB / 32);   // warp per node
    const int gblocks = (n + GR - 1) / GR;                 // 625

    // 1: layer-1 GEMM first (independent of graph build; profiler lands on layer kernels)
    k_gemm128<<<gblocks, TB, GEMM_SMEM>>>(x, W1, g_h, n);
    // 2-5: graph structure + reg_loss hash
    k_init<<<2048, TB>>>();
    k_edge1<<<eblocks, TB>>>(src, dst, E, n);
    k_scan<<<1, 1024>>>(n, E);
    k_edge2<<<eblocks, TB>>>(src, dst, E, n);
    // 6: layer-1 aggregation
    k_agg128<<<wblocks, TB>>>(g_h, b1, g_y, n);
    // 7-8: layer 2
    k_gemm128<<<gblocks, TB, GEMM_SMEM>>>(g_y, W2, g_h, n);
    k_agg128<<<wblocks, TB>>>(g_h, b2, g_y, n);
    // 9-10: layer 3 + log_softmax (+ reg write)
    k_gemm40<<<444, TB>>>(g_y, W3, g_h3, n);
    k_agg40<<<wblocks, TB>>>(g_h3, b3, out, n, out_size - 1);
}